// round 14
// baseline (speedup 1.0000x reference)
#include <cuda_runtime.h>

// LIF scan: T=16, N = 4,194,304 sites. HBM-bound streaming (256 MiB in, 256 MiB out).
// Roofline-pinned at ~6.3 TB/s (80% of spec) across 13 rounds; all scheduling,
// geometry, and access-width axes are non-binding. FINAL micro-probe: store
// policy third point — __stwt (st.global.wt, write-through). Unlike .cs and
// default (both L2 write-back), .wt bypasses the L2 dirty-line machinery so
// the DRAM controller, not L2's drain scheduler, owns write interleaving.
// Writes are never re-read, so there is no reuse downside. Expected neutral;
// converged .cs kernel is the fallback.

#ifndef LIF_T
#define LIF_T 16
#endif
#define TBATCH 8

__global__ void __launch_bounds__(256) lif_kernel(
    const float4* __restrict__ in,   // [T, N/4] float4
    float4* __restrict__ out,        // [T, N/4] float4
    int n4)                          // N/4
{
    const int i = blockIdx.x * blockDim.x + threadIdx.x;
    if (i >= n4) return;

    const float decay = 0.5f;
    const float thr   = 1.0f;

    float vx = 0.0f, vy = 0.0f, vz = 0.0f, vw = 0.0f;

    const float4* __restrict__ ip = in + i;
    float4* __restrict__ op = out + i;

    #pragma unroll
    for (int tb = 0; tb < LIF_T; tb += TBATCH) {
        // Phase 1: 8 front-batched streaming loads (independent LDG.128)
        float4 x[TBATCH];
        #pragma unroll
        for (int j = 0; j < TBATCH; ++j) {
            x[j] = __ldcs(ip + (size_t)(tb + j) * n4);
        }

        // Phase 2: serial LIF chain entirely in registers
        #pragma unroll
        for (int j = 0; j < TBATCH; ++j) {
            vx = fmaf(vx, decay, x[j].x);
            vy = fmaf(vy, decay, x[j].y);
            vz = fmaf(vz, decay, x[j].z);
            vw = fmaf(vw, decay, x[j].w);

            const float sx = (vx >= thr) ? 1.0f : 0.0f;
            const float sy = (vy >= thr) ? 1.0f : 0.0f;
            const float sz = (vz >= thr) ? 1.0f : 0.0f;
            const float sw = (vw >= thr) ? 1.0f : 0.0f;

            vx -= sx * thr;
            vy -= sy * thr;
            vz -= sz * thr;
            vw -= sw * thr;

            x[j].x = sx; x[j].y = sy; x[j].z = sz; x[j].w = sw;
        }

        // Phase 3: 8 batched WRITE-THROUGH stores (bypass L2 write-back)
        #pragma unroll
        for (int j = 0; j < TBATCH; ++j) {
            __stwt(op + (size_t)(tb + j) * n4, x[j]);
        }
    }
}

extern "C" void kernel_launch(void* const* d_in, const int* in_sizes, int n_in,
                              void* d_out, int out_size)
{
    const float* in = (const float*)d_in[0];
    float* out = (float*)d_out;

    const int total = in_sizes[0];            // T * N = 67,108,864
    const int n = total / LIF_T;              // N = 4,194,304 (sites)
    const int n4 = n / 4;                     // 1,048,576 float4 lanes

    const int block = 256;
    const int grid = (n4 + block - 1) / block;   // 4096

    lif_kernel<<<grid, block>>>((const float4*)in, (float4*)out, n4);
}

// round 15
// speedup vs baseline: 1.0249x; 1.0249x over previous
#include <cuda_runtime.h>

// LIF scan: T=16, N = 4,194,304 sites. HBM-bound streaming (256 MiB in, 256 MiB out).
// FINAL (converged, reproduced 4x: ncu 75.8-76.6us, bench 82.3-82.4us best).
// Fourteen rounds / nine axes, ALL non-binding: occupancy (31-85%),
// per-thread MLP (2-16), R/W warp phasing, wave structure (1 vs 3.5),
// per-CTA row footprint (4-16 KiB), store policy (.cs/default/.wt),
// block size (256/512/1024), access width (128-/256-bit LDG/STG), wave tail.
// Every variant pins at 6.27-6.39 TB/s (~80% of 8 TB/s spec). Traffic is
// provably minimal (serial recurrence: exactly one read + one write per
// element, zero exploitable reuse); compute/issue < 11%. Residual ~20% is
// HBM-controller-level (refresh + 50/50 R/W bus turnaround) — unreachable
// from the SM. This is the mixed-stream DRAM roofline.
//
// Config: one thread per 4 sites (float4), time loop in 2 groups of 8:
// 8 front-batched LDG.128 -> serial v-chain in registers -> 8 batched
// STG.128, streaming (.cs) hints both directions. block=256, grid=4096.

#ifndef LIF_T
#define LIF_T 16
#endif
#define TBATCH 8

__global__ void __launch_bounds__(256) lif_kernel(
    const float4* __restrict__ in,   // [T, N/4] float4
    float4* __restrict__ out,        // [T, N/4] float4
    int n4)                          // N/4
{
    const int i = blockIdx.x * blockDim.x + threadIdx.x;
    if (i >= n4) return;

    const float decay = 0.5f;
    const float thr   = 1.0f;

    float vx = 0.0f, vy = 0.0f, vz = 0.0f, vw = 0.0f;

    const float4* __restrict__ ip = in + i;
    float4* __restrict__ op = out + i;

    #pragma unroll
    for (int tb = 0; tb < LIF_T; tb += TBATCH) {
        // Phase 1: 8 front-batched streaming loads (independent LDG.128)
        float4 x[TBATCH];
        #pragma unroll
        for (int j = 0; j < TBATCH; ++j) {
            x[j] = __ldcs(ip + (size_t)(tb + j) * n4);
        }

        // Phase 2: serial LIF chain entirely in registers
        #pragma unroll
        for (int j = 0; j < TBATCH; ++j) {
            vx = fmaf(vx, decay, x[j].x);
            vy = fmaf(vy, decay, x[j].y);
            vz = fmaf(vz, decay, x[j].z);
            vw = fmaf(vw, decay, x[j].w);

            const float sx = (vx >= thr) ? 1.0f : 0.0f;
            const float sy = (vy >= thr) ? 1.0f : 0.0f;
            const float sz = (vz >= thr) ? 1.0f : 0.0f;
            const float sw = (vw >= thr) ? 1.0f : 0.0f;

            vx -= sx * thr;
            vy -= sy * thr;
            vz -= sz * thr;
            vw -= sw * thr;

            x[j].x = sx; x[j].y = sy; x[j].z = sz; x[j].w = sw;
        }

        // Phase 3: 8 batched streaming stores (STG.128)
        #pragma unroll
        for (int j = 0; j < TBATCH; ++j) {
            __stcs(op + (size_t)(tb + j) * n4, x[j]);
        }
    }
}

extern "C" void kernel_launch(void* const* d_in, const int* in_sizes, int n_in,
                              void* d_out, int out_size)
{
    const float* in = (const float*)d_in[0];
    float* out = (float*)d_out;

    const int total = in_sizes[0];            // T * N = 67,108,864
    const int n = total / LIF_T;              // N = 4,194,304 (sites)
    const int n4 = n / 4;                     // 1,048,576 float4 lanes

    const int block = 256;
    const int grid = (n4 + block - 1) / block;   // 4096

    lif_kernel<<<grid, block>>>((const float4*)in, (float4*)out, n4);
}